// round 13
// baseline (speedup 1.0000x reference)
#include <cuda_runtime.h>
#include <cuda_bf16.h>
#include <math.h>

#define D 128
#define NSLOT 8
#define OUTW 1288   // 2*D + NSLOT*D + NSLOT

// B operands, per-lane mma fragment layout, hi/lo interleaved:
__device__ uint4 g_BU[D * D / 4];   // B[k][n] = M[k][n]  (M = Wq^T Wk)
__device__ uint4 g_BF[D * D / 4];   // B[k][n] = Wf[n][k]

// ---------------------------------------------------------------------------
// helpers
// ---------------------------------------------------------------------------
__device__ __forceinline__ float dot4(float4 a, float4 b) {
    return fmaf(a.x, b.x, fmaf(a.y, b.y, fmaf(a.z, b.z, a.w * b.w)));
}
__device__ __forceinline__ unsigned pack_bf(float x, float y) {
    unsigned r;
    asm("cvt.rn.bf16x2.f32 %0, %1, %2;" : "=r"(r) : "f"(y), "f"(x));
    return r;
}
__device__ __forceinline__ float lo_f(unsigned r) { return __uint_as_float(r << 16); }
__device__ __forceinline__ float hi_f(unsigned r) { return __uint_as_float(r & 0xffff0000u); }

__device__ __forceinline__ unsigned smem_u32(const void* p) {
    unsigned a;
    asm("{ .reg .u64 t; cvta.to.shared.u64 t, %1; cvt.u32.u64 %0, t; }" : "=r"(a) : "l"(p));
    return a;
}
__device__ __forceinline__ uint4 ldm_x4(unsigned addr) {
    uint4 r;
    asm volatile("ldmatrix.sync.aligned.m8n8.x4.shared.b16 {%0,%1,%2,%3}, [%4];"
                 : "=r"(r.x), "=r"(r.y), "=r"(r.z), "=r"(r.w) : "r"(addr));
    return r;
}
__device__ __forceinline__ void mma_bf16(float* c, uint4 a, unsigned b0, unsigned b1) {
    asm volatile(
        "mma.sync.aligned.m16n8k16.row.col.f32.bf16.bf16.f32 "
        "{%0,%1,%2,%3}, {%4,%5,%6,%7}, {%8,%9}, {%0,%1,%2,%3};"
        : "+f"(c[0]), "+f"(c[1]), "+f"(c[2]), "+f"(c[3])
        : "r"(a.x), "r"(a.y), "r"(a.z), "r"(a.w), "r"(b0), "r"(b1));
}
__device__ __forceinline__ void cp_async16(unsigned dst, const void* src) {
    asm volatile("cp.async.cg.shared.global [%0], [%1], 16;" :: "r"(dst), "l"(src));
}

// fragment address math for B (16x8 k×n tile), PTX ISA m16n8k16 ownership
__device__ __forceinline__ void store_b_frag(uint4* arr, int k, int n,
                                             unsigned short hb, unsigned short lb) {
    int lane = ((n & 7) << 2) + ((k & 7) >> 1);
    int fs = ((k >> 4) << 4) + (n >> 3);
    int base = (fs * 32 + lane) * 8;
    int off = (((k >> 3) & 1) << 1) + (k & 1);
    ((unsigned short*)arr)[base + off] = hb;
    ((unsigned short*)arr)[base + 4 + off] = lb;
}

// ---------------------------------------------------------------------------
// prep
// ---------------------------------------------------------------------------
__global__ void prep_kernel(const float* __restrict__ Wq,
                            const float* __restrict__ Wk,
                            const float* __restrict__ Wf) {
    int d = blockIdx.x;
    int t = threadIdx.x;
    if (d < D) {
        float a0 = 0.f, a1 = 0.f, a2 = 0.f, a3 = 0.f;
#pragma unroll 8
        for (int e = 0; e < D; e += 4) {
            a0 = fmaf(Wq[(e + 0) * D + d], Wk[(e + 0) * D + t], a0);
            a1 = fmaf(Wq[(e + 1) * D + d], Wk[(e + 1) * D + t], a1);
            a2 = fmaf(Wq[(e + 2) * D + d], Wk[(e + 2) * D + t], a2);
            a3 = fmaf(Wq[(e + 3) * D + d], Wk[(e + 3) * D + t], a3);
        }
        float m = (a0 + a1) + (a2 + a3);
        __nv_bfloat16 hb = __float2bfloat16(m);
        float lo = m - __bfloat162float(hb);
        __nv_bfloat16 lb = __float2bfloat16(lo);
        store_b_frag(g_BU, d, t, *(unsigned short*)&hb, *(unsigned short*)&lb);
    } else {
        int n = d - D;
        float m = Wf[n * D + t];
        __nv_bfloat16 hb = __float2bfloat16(m);
        float lo = m - __bfloat162float(hb);
        __nv_bfloat16 lb = __float2bfloat16(lo);
        store_b_frag(g_BF, t, n, *(unsigned short*)&hb, *(unsigned short*)&lb);
    }
}

// ---------------------------------------------------------------------------
// mma sub-kernel (A/S staged in smA, swizzled bf16 hi/lo)
// ---------------------------------------------------------------------------
__device__ __forceinline__ void mma_phase(const char* smA, const uint4* __restrict__ Bint,
                                          int wm, int wn, int lane, float acc[8][4]) {
#pragma unroll
    for (int j = 0; j < 8; j++)
#pragma unroll
        for (int q = 0; q < 4; q++) acc[j][q] = 0.f;

    const int lrow = wm * 16 + (lane & 15);
    const unsigned sb = smem_u32(smA);
    const uint4* bp = Bint + wn * 8 * 32 + lane;

#pragma unroll
    for (int kt = 0; kt < 8; kt++) {
        const int chunk = kt * 2 + (lane >> 4);
        const unsigned ah = sb + lrow * 256 + ((chunk ^ (lrow & 7)) << 4);
        uint4 h = ldm_x4(ah);
        uint4 l = ldm_x4(ah + 16384);

        uint4 bb0[4];
#pragma unroll
        for (int nt = 0; nt < 4; nt++) bb0[nt] = bp[(kt * 16 + nt) * 32];
        uint4 bb1[4];
#pragma unroll
        for (int nt = 0; nt < 4; nt++) bb1[nt] = bp[(kt * 16 + 4 + nt) * 32];

#pragma unroll
        for (int nt = 0; nt < 4; nt++) {
            mma_bf16(acc[nt], h, bb0[nt].x, bb0[nt].y);
            mma_bf16(acc[nt], h, bb0[nt].z, bb0[nt].w);
            mma_bf16(acc[nt], l, bb0[nt].x, bb0[nt].y);
        }
#pragma unroll
        for (int nt = 0; nt < 4; nt++) {
            mma_bf16(acc[4 + nt], h, bb1[nt].x, bb1[nt].y);
            mma_bf16(acc[4 + nt], h, bb1[nt].z, bb1[nt].w);
            mma_bf16(acc[4 + nt], l, bb1[nt].x, bb1[nt].y);
        }
    }
}

// ---------------------------------------------------------------------------
// FUSED kernel. smem (96KB): [0,32K) bf16 staging, [32K,64K) f32 U/S,
// [64K,96K) slot prefetch (warp w -> batch row brow + w*8).
// ---------------------------------------------------------------------------
__global__ __launch_bounds__(256, 2)
void fused_kernel(const float* __restrict__ state, const float* __restrict__ slots,
                  const float* __restrict__ acts, const float* __restrict__ Wg_w,
                  const float* __restrict__ Wg_b, const uint4* __restrict__ BU,
                  const uint4* __restrict__ BF, float* __restrict__ out) {
    extern __shared__ char smem[];
    char* smA = smem;
    float* smU = (float*)(smem + 32768);
    char* smP = smem + 65536;

    const int tid = threadIdx.x;
    const int warp = tid >> 5;
    const int lane = tid & 31;
    const int wm = warp & 3;
    const int wn = warp >> 2;
    const int brow = blockIdx.x * 64;

    // ======== phase 1: stage state -> bf16 smem ========
#pragma unroll
    for (int i = 0; i < 8; i++) {
        int idx = tid + i * 256;
        int row = idx >> 5;
        int c4 = idx & 31;
        float4 v = ((const float4*)state)[(size_t)(brow + row) * 32 + c4];
        unsigned h01 = pack_bf(v.x, v.y);
        unsigned h23 = pack_bf(v.z, v.w);
        unsigned l01 = pack_bf(v.x - lo_f(h01), v.y - hi_f(h01));
        unsigned l23 = pack_bf(v.z - lo_f(h23), v.w - hi_f(h23));
        int chunk = c4 >> 1, half = c4 & 1;
        int off = row * 256 + ((chunk ^ (row & 7)) << 4) + (half << 3);
        *(uint2*)(smA + off) = make_uint2(h01, h23);
        *(uint2*)(smA + 16384 + off) = make_uint2(l01, l23);
    }

    // prefetch first ew row's slots (overlaps GEMM1)
    {
        const char* src = (const char*)(slots + (size_t)(brow + warp * 8) * NSLOT * D);
        unsigned dstb = smem_u32(smP + warp * 4096);
#pragma unroll
        for (int it = 0; it < 8; it++) {
            int idx = (it * 32 + lane) * 16;
            cp_async16(dstb + idx, src + idx);
        }
        asm volatile("cp.async.commit_group;" ::: "memory");
    }
    __syncthreads();

    // ======== GEMM1: U = state @ M -> smU ========
    {
        float acc[8][4];
        mma_phase(smA, BU, wm, wn, lane, acc);
        const int row0 = wm * 16 + (lane >> 2);
        const int cb = (lane & 3) << 1;
#pragma unroll
        for (int nt = 0; nt < 8; nt++) {
            const int col = wn * 64 + nt * 8 + cb;
            *(float2*)(smU + row0 * 128 + col) = make_float2(acc[nt][0], acc[nt][1]);
            *(float2*)(smU + (row0 + 8) * 128 + col) = make_float2(acc[nt][2], acc[nt][3]);
        }
    }
    __syncthreads();

    // ======== phase 2: ew (warp w owns rows w*8..w*8+7) ========
    asm volatile("cp.async.wait_group 0;" ::: "memory");
    const float4 wg0 = ((const float4*)Wg_w)[lane];
    const float4 wg1 = ((const float4*)Wg_w)[32 + lane];
    const float wgb = Wg_b[0];

#pragma unroll 1
    for (int r = 0; r < 8; r++) {
        const int lrow = warp * 8 + r;
        const int b = brow + lrow;

        // reconstruct state from smA (hi + lo), cols lane*4..lane*4+3
        float4 sv;
        {
            int chunk = lane >> 1, half = lane & 1;
            int off = lrow * 256 + ((chunk ^ (lrow & 7)) << 4) + (half << 3);
            uint2 hu = *(uint2*)(smA + off);
            uint2 lu = *(uint2*)(smA + 16384 + off);
            sv = make_float4(lo_f(hu.x) + lo_f(lu.x), hi_f(hu.x) + hi_f(lu.x),
                             lo_f(hu.y) + lo_f(lu.y), hi_f(hu.y) + hi_f(lu.y));
        }
        const float4 uv = *(const float4*)(smU + lrow * 128 + lane * 4);
        float4 sl[NSLOT];
        if (r == 0) {
            const float4* sp = (const float4*)(smP + warp * 4096);
#pragma unroll
            for (int n = 0; n < NSLOT; n++) sl[n] = sp[n * 32 + lane];
        } else {
            const float4* slp = (const float4*)slots + (size_t)b * 256;
#pragma unroll
            for (int n = 0; n < NSLOT; n++) sl[n] = __ldcs(slp + n * 32 + lane);
        }
        const float4 aa = ((const float4*)acts)[(size_t)b * 2];
        const float4 ab = ((const float4*)acts)[(size_t)b * 2 + 1];

        float a_[NSLOT] = {aa.x, aa.y, aa.z, aa.w, ab.x, ab.y, ab.z, ab.w};
        float na[NSLOT];
#pragma unroll
        for (int n = 0; n < NSLOT; n++) na[n] = a_[n] * 0.95f;

        float4 wm4 = make_float4(0.f, 0.f, 0.f, 0.f);
#pragma unroll
        for (int n = 0; n < NSLOT; n++) {
            wm4.x = fmaf(na[n], sl[n].x, wm4.x);
            wm4.y = fmaf(na[n], sl[n].y, wm4.y);
            wm4.z = fmaf(na[n], sl[n].z, wm4.z);
            wm4.w = fmaf(na[n], sl[n].w, wm4.w);
        }
        float gdp = fmaf(0.125f, dot4(wm4, wg1), dot4(sv, wg0));
        float sn2 = dot4(sv, sv);
        float du[NSLOT], ds[NSLOT], qn[NSLOT];
#pragma unroll
        for (int n = 0; n < NSLOT; n++) {
            du[n] = dot4(uv, sl[n]);
            ds[n] = dot4(sv, sl[n]);
            qn[n] = dot4(sl[n], sl[n]);
        }

#pragma unroll
        for (int o = 16; o; o >>= 1) {
#pragma unroll
            for (int n = 0; n < NSLOT; n++) {
                du[n] += __shfl_xor_sync(0xFFFFFFFFu, du[n], o);
                ds[n] += __shfl_xor_sync(0xFFFFFFFFu, ds[n], o);
                qn[n] += __shfl_xor_sync(0xFFFFFFFFu, qn[n], o);
            }
            sn2 += __shfl_xor_sync(0xFFFFFFFFu, sn2, o);
            gdp += __shfl_xor_sync(0xFFFFFFFFu, gdp, o);
        }

        const float gd = gdp + wgb;
        const float gate = 1.f / (1.f + __expf(-gd));
        const float stn = fmaxf(sqrtf(sn2), 1e-12f);
        const float inv_stn = 1.f / stn;

        const float inv_sqrt_d = 0.08838834764831845f;
        float attn[NSLOT];
        float mx = -INFINITY;
#pragma unroll
        for (int n = 0; n < NSLOT; n++) {
            attn[n] = du[n] * inv_sqrt_d * a_[n];
            mx = fmaxf(mx, attn[n]);
        }
        float se = 0.f;
#pragma unroll
        for (int n = 0; n < NSLOT; n++) {
            attn[n] = __expf(attn[n] - mx);
            se += attn[n];
        }
        const float inv_se = 1.f / se;

        float simmax = -INFINITY;
#pragma unroll
        for (int n = 0; n < NSLOT; n++) {
            float m = (na[n] > 0.01f) ? 1.f : 0.f;
            float c = ds[n] * inv_stn / fmaxf(sqrtf(qn[n]), 1e-12f);
            simmax = fmaxf(simmax, c * m);
        }
        const float novelty = 1.f - fminf(fmaxf(simmax, 0.f), 1.f);
        const bool do_write = (novelty > 0.3f) || (gate > 0.5f);

        int weakest = 0;
        float mn = na[0];
#pragma unroll
        for (int n = 1; n < NSLOT; n++)
            if (na[n] < mn) { mn = na[n]; weakest = n; }
        const int sel = do_write ? weakest : -1;

        float swv[NSLOT];
        float swmx = -INFINITY;
#pragma unroll
        for (int n = 0; n < NSLOT; n++) {
            swv[n] = (n == sel) ? 1.f : na[n];
            swmx = fmaxf(swmx, swv[n]);
        }
        float ssum = 0.f;
#pragma unroll
        for (int n = 0; n < NSLOT; n++) {
            swv[n] = __expf(swv[n] - swmx);
            ssum += swv[n];
        }
        const float inv_ss = 1.f / ssum;

        float4* orow4 = (float4*)(out + (size_t)b * OUTW);
        float4 ro = make_float4(0.f, 0.f, 0.f, 0.f);
        float4 sm = make_float4(0.f, 0.f, 0.f, 0.f);
#pragma unroll
        for (int n = 0; n < NSLOT; n++) {
            const float wa = attn[n] * inv_se;
            const float ws = swv[n] * inv_ss;
            float4 x = sl[n];
            float4 v = (n == sel) ? sv : x;
            ro.x = fmaf(wa, x.x, ro.x);  ro.y = fmaf(wa, x.y, ro.y);
            ro.z = fmaf(wa, x.z, ro.z);  ro.w = fmaf(wa, x.w, ro.w);
            sm.x = fmaf(ws, v.x, sm.x);  sm.y = fmaf(ws, v.y, sm.y);
            sm.z = fmaf(ws, v.z, sm.z);  sm.w = fmaf(ws, v.w, sm.w);
            __stcs(orow4 + 64 + n * 32 + lane, v);
        }
        __stcs(orow4 + lane, ro);
        *(float4*)(smU + lrow * 128 + lane * 4) = sm;   // S in-place
        if (lane < NSLOT) {
            float v = (lane == sel) ? 1.f : na[lane];
            out[(size_t)b * OUTW + 2 * D + NSLOT * D + lane] = v;
        }
    }
    __syncthreads();

    // ======== phase 3: stage S (smU) -> bf16 smem ========
#pragma unroll
    for (int i = 0; i < 8; i++) {
        int idx = tid + i * 256;
        int row = idx >> 5;
        int c4 = idx & 31;
        float4 v = *(const float4*)(smU + row * 128 + c4 * 4);
        unsigned h01 = pack_bf(v.x, v.y);
        unsigned h23 = pack_bf(v.z, v.w);
        unsigned l01 = pack_bf(v.x - lo_f(h01), v.y - hi_f(h01));
        unsigned l23 = pack_bf(v.z - lo_f(h23), v.w - hi_f(h23));
        int chunk = c4 >> 1, half = c4 & 1;
        int off = row * 256 + ((chunk ^ (row & 7)) << 4) + (half << 3);
        *(uint2*)(smA + off) = make_uint2(h01, h23);
        *(uint2*)(smA + 16384 + off) = make_uint2(l01, l23);
    }
    __syncthreads();

    // ======== GEMM2: summary = S @ Wf^T -> out[:,128:256] ========
    {
        float acc[8][4];
        mma_phase(smA, BF, wm, wn, lane, acc);
        const int row = brow + wm * 16 + (lane >> 2);
        const int cb = (lane & 3) << 1;
#pragma unroll
        for (int nt = 0; nt < 8; nt++) {
            const int col = D + wn * 64 + nt * 8 + cb;
            float* cp = out + (size_t)row * OUTW + col;
            *(float2*)cp = make_float2(acc[nt][0], acc[nt][1]);
            *(float2*)(cp + 8 * OUTW) = make_float2(acc[nt][2], acc[nt][3]);
        }
    }
}

// ---------------------------------------------------------------------------
extern "C" void kernel_launch(void* const* d_in, const int* in_sizes, int n_in,
                              void* d_out, int out_size) {
    const float* state = (const float*)d_in[0];
    const float* slots = (const float*)d_in[1];
    const float* acts  = (const float*)d_in[2];
    const float* Wq    = (const float*)d_in[3];
    const float* Wk    = (const float*)d_in[4];
    const float* Wg_w  = (const float*)d_in[5];
    const float* Wg_b  = (const float*)d_in[6];
    const float* Wf    = (const float*)d_in[7];
    float* out = (float*)d_out;

    const int B = in_sizes[0] / D;

    void *pBU, *pBF;
    cudaGetSymbolAddress(&pBU, g_BU);
    cudaGetSymbolAddress(&pBF, g_BF);

    static int attr_set = 0;
    if (!attr_set) {
        cudaFuncSetAttribute(fused_kernel,
                             cudaFuncAttributeMaxDynamicSharedMemorySize, 98304);
        attr_set = 1;
    }

    prep_kernel<<<256, 128>>>(Wq, Wk, Wf);
    fused_kernel<<<B / 64, 256, 98304>>>(state, slots, acts, Wg_w, Wg_b,
                                         (const uint4*)pBU, (const uint4*)pBF, out);
}

// round 14
// speedup vs baseline: 1.0862x; 1.0862x over previous
#include <cuda_runtime.h>
#include <cuda_bf16.h>
#include <math.h>

#define D 128
#define NSLOT 8
#define OUTW 1288   // 2*D + NSLOT*D + NSLOT

// B operands, per-lane mma fragment layout, hi/lo interleaved:
__device__ uint4 g_BU[D * D / 4];   // B[k][n] = M[k][n]  (M = Wq^T Wk)
__device__ uint4 g_BF[D * D / 4];   // B[k][n] = Wf[n][k]

// ---------------------------------------------------------------------------
// helpers
// ---------------------------------------------------------------------------
__device__ __forceinline__ float dot4(float4 a, float4 b) {
    return fmaf(a.x, b.x, fmaf(a.y, b.y, fmaf(a.z, b.z, a.w * b.w)));
}
__device__ __forceinline__ unsigned pack_bf(float x, float y) {
    unsigned r;
    asm("cvt.rn.bf16x2.f32 %0, %1, %2;" : "=r"(r) : "f"(y), "f"(x));
    return r;
}
__device__ __forceinline__ float lo_f(unsigned r) { return __uint_as_float(r << 16); }
__device__ __forceinline__ float hi_f(unsigned r) { return __uint_as_float(r & 0xffff0000u); }

__device__ __forceinline__ unsigned smem_u32(const void* p) {
    unsigned a;
    asm("{ .reg .u64 t; cvta.to.shared.u64 t, %1; cvt.u32.u64 %0, t; }" : "=r"(a) : "l"(p));
    return a;
}
__device__ __forceinline__ uint4 ldm_x4(unsigned addr) {
    uint4 r;
    asm volatile("ldmatrix.sync.aligned.m8n8.x4.shared.b16 {%0,%1,%2,%3}, [%4];"
                 : "=r"(r.x), "=r"(r.y), "=r"(r.z), "=r"(r.w) : "r"(addr));
    return r;
}
__device__ __forceinline__ void mma_bf16(float* c, uint4 a, unsigned b0, unsigned b1) {
    asm volatile(
        "mma.sync.aligned.m16n8k16.row.col.f32.bf16.bf16.f32 "
        "{%0,%1,%2,%3}, {%4,%5,%6,%7}, {%8,%9}, {%0,%1,%2,%3};"
        : "+f"(c[0]), "+f"(c[1]), "+f"(c[2]), "+f"(c[3])
        : "r"(a.x), "r"(a.y), "r"(a.z), "r"(a.w), "r"(b0), "r"(b1));
}
__device__ __forceinline__ void cp_async16(unsigned dst, const void* src) {
    asm volatile("cp.async.cg.shared.global [%0], [%1], 16;" :: "r"(dst), "l"(src));
}
__device__ __forceinline__ void cp_commit() {
    asm volatile("cp.async.commit_group;" ::: "memory");
}

// fragment address math for B (16x8 k×n tile), PTX ISA m16n8k16 ownership
__device__ __forceinline__ void store_b_frag(uint4* arr, int k, int n,
                                             unsigned short hb, unsigned short lb) {
    int lane = ((n & 7) << 2) + ((k & 7) >> 1);
    int fs = ((k >> 4) << 4) + (n >> 3);
    int base = (fs * 32 + lane) * 8;
    int off = (((k >> 3) & 1) << 1) + (k & 1);
    ((unsigned short*)arr)[base + off] = hb;
    ((unsigned short*)arr)[base + 4 + off] = lb;
}

// ---------------------------------------------------------------------------
// prep
// ---------------------------------------------------------------------------
__global__ void prep_kernel(const float* __restrict__ Wq,
                            const float* __restrict__ Wk,
                            const float* __restrict__ Wf) {
    int d = blockIdx.x;
    int t = threadIdx.x;
    if (d < D) {
        float a0 = 0.f, a1 = 0.f, a2 = 0.f, a3 = 0.f;
#pragma unroll 8
        for (int e = 0; e < D; e += 4) {
            a0 = fmaf(Wq[(e + 0) * D + d], Wk[(e + 0) * D + t], a0);
            a1 = fmaf(Wq[(e + 1) * D + d], Wk[(e + 1) * D + t], a1);
            a2 = fmaf(Wq[(e + 2) * D + d], Wk[(e + 2) * D + t], a2);
            a3 = fmaf(Wq[(e + 3) * D + d], Wk[(e + 3) * D + t], a3);
        }
        float m = (a0 + a1) + (a2 + a3);
        __nv_bfloat16 hb = __float2bfloat16(m);
        float lo = m - __bfloat162float(hb);
        __nv_bfloat16 lb = __float2bfloat16(lo);
        store_b_frag(g_BU, d, t, *(unsigned short*)&hb, *(unsigned short*)&lb);
    } else {
        int n = d - D;
        float m = Wf[n * D + t];
        __nv_bfloat16 hb = __float2bfloat16(m);
        float lo = m - __bfloat162float(hb);
        __nv_bfloat16 lb = __float2bfloat16(lo);
        store_b_frag(g_BF, t, n, *(unsigned short*)&hb, *(unsigned short*)&lb);
    }
}

// ---------------------------------------------------------------------------
// mma sub-kernel (A/S staged in smA, swizzled bf16 hi/lo)
// ---------------------------------------------------------------------------
__device__ __forceinline__ void mma_phase(const char* smA, const uint4* __restrict__ Bint,
                                          int wm, int wn, int lane, float acc[8][4]) {
#pragma unroll
    for (int j = 0; j < 8; j++)
#pragma unroll
        for (int q = 0; q < 4; q++) acc[j][q] = 0.f;

    const int lrow = wm * 16 + (lane & 15);
    const unsigned sb = smem_u32(smA);
    const uint4* bp = Bint + wn * 8 * 32 + lane;

#pragma unroll
    for (int kt = 0; kt < 8; kt++) {
        const int chunk = kt * 2 + (lane >> 4);
        const unsigned ah = sb + lrow * 256 + ((chunk ^ (lrow & 7)) << 4);
        uint4 h = ldm_x4(ah);
        uint4 l = ldm_x4(ah + 16384);

        uint4 bb0[4];
#pragma unroll
        for (int nt = 0; nt < 4; nt++) bb0[nt] = bp[(kt * 16 + nt) * 32];
        uint4 bb1[4];
#pragma unroll
        for (int nt = 0; nt < 4; nt++) bb1[nt] = bp[(kt * 16 + 4 + nt) * 32];

#pragma unroll
        for (int nt = 0; nt < 4; nt++) {
            mma_bf16(acc[nt], h, bb0[nt].x, bb0[nt].y);
            mma_bf16(acc[nt], h, bb0[nt].z, bb0[nt].w);
            mma_bf16(acc[nt], l, bb0[nt].x, bb0[nt].y);
        }
#pragma unroll
        for (int nt = 0; nt < 4; nt++) {
            mma_bf16(acc[4 + nt], h, bb1[nt].x, bb1[nt].y);
            mma_bf16(acc[4 + nt], h, bb1[nt].z, bb1[nt].w);
            mma_bf16(acc[4 + nt], l, bb1[nt].x, bb1[nt].y);
        }
    }
}

// ---------------------------------------------------------------------------
// FUSED kernel. smem (96KB): [0,32K) bf16 staging (doubles as prefetch buf P1
// during ew), [32K,64K) f32 U/S, [64K,96K) prefetch buf P0.
// Warp-private 4KB slot buffers; ping-pong by row parity, depth-1 pipeline.
// ---------------------------------------------------------------------------
__global__ __launch_bounds__(256, 2)
void fused_kernel(const float* __restrict__ state, const float* __restrict__ slots,
                  const float* __restrict__ acts, const float* __restrict__ Wg_w,
                  const float* __restrict__ Wg_b, const uint4* __restrict__ BU,
                  const uint4* __restrict__ BF, float* __restrict__ out) {
    extern __shared__ char smem[];
    char* smA = smem;
    float* smU = (float*)(smem + 32768);
    char* smP = smem + 65536;

    const int tid = threadIdx.x;
    const int warp = tid >> 5;
    const int lane = tid & 31;
    const int wm = warp & 3;
    const int wn = warp >> 2;
    const int brow = blockIdx.x * 64;

    const unsigned pbuf0 = smem_u32(smP + warp * 4096);   // even rows
    const unsigned pbuf1 = smem_u32(smA + warp * 4096);   // odd rows (valid post-GEMM1)
    const char* slot_base = (const char*)(slots + (size_t)(brow + warp * 8) * NSLOT * D);

    // ======== phase 1: stage state -> bf16 smem ========
#pragma unroll
    for (int i = 0; i < 8; i++) {
        int idx = tid + i * 256;
        int row = idx >> 5;
        int c4 = idx & 31;
        float4 v = ((const float4*)state)[(size_t)(brow + row) * 32 + c4];
        unsigned h01 = pack_bf(v.x, v.y);
        unsigned h23 = pack_bf(v.z, v.w);
        unsigned l01 = pack_bf(v.x - lo_f(h01), v.y - hi_f(h01));
        unsigned l23 = pack_bf(v.z - lo_f(h23), v.w - hi_f(h23));
        int chunk = c4 >> 1, half = c4 & 1;
        int off = row * 256 + ((chunk ^ (row & 7)) << 4) + (half << 3);
        *(uint2*)(smA + off) = make_uint2(h01, h23);
        *(uint2*)(smA + 16384 + off) = make_uint2(l01, l23);
    }

    // prefetch row 0 slots -> P0 (overlaps GEMM1)
#pragma unroll
    for (int it = 0; it < 8; it++) {
        int idx = (it * 32 + lane) * 16;
        cp_async16(pbuf0 + idx, slot_base + idx);
    }
    cp_commit();
    __syncthreads();

    // ======== GEMM1: U = state @ M -> smU ========
    {
        float acc[8][4];
        mma_phase(smA, BU, wm, wn, lane, acc);
        const int row0 = wm * 16 + (lane >> 2);
        const int cb = (lane & 3) << 1;
#pragma unroll
        for (int nt = 0; nt < 8; nt++) {
            const int col = wn * 64 + nt * 8 + cb;
            *(float2*)(smU + row0 * 128 + col) = make_float2(acc[nt][0], acc[nt][1]);
            *(float2*)(smU + (row0 + 8) * 128 + col) = make_float2(acc[nt][2], acc[nt][3]);
        }
    }
    __syncthreads();   // smA reads done; smA now reusable as P1

    // prefetch row 1 slots -> P1
#pragma unroll
    for (int it = 0; it < 8; it++) {
        int idx = (it * 32 + lane) * 16;
        cp_async16(pbuf1 + idx, slot_base + 4096 + idx);
    }
    cp_commit();

    const float4 wg0 = ((const float4*)Wg_w)[lane];
    const float4 wg1 = ((const float4*)Wg_w)[32 + lane];
    const float wgb = Wg_b[0];

    // ======== phase 2: ew (warp w owns rows w*8..w*8+7), pipelined ========
#pragma unroll 1
    for (int r = 0; r < 8; r++) {
        const int lrow = warp * 8 + r;
        const int b = brow + lrow;
        const unsigned pb = (r & 1) ? pbuf1 : pbuf0;

        const float4 sv = ((const float4*)state)[(size_t)b * 32 + lane];
        const float4 uv = *(const float4*)(smU + lrow * 128 + lane * 4);
        const float4 aa = ((const float4*)acts)[(size_t)b * 2];
        const float4 ab = ((const float4*)acts)[(size_t)b * 2 + 1];

        // wait for this row's slots, read them, then refill buffer with row r+2
        asm volatile("cp.async.wait_group 1;" ::: "memory");
        float4 sl[NSLOT];
#pragma unroll
        for (int n = 0; n < NSLOT; n++)
            sl[n] = *(const float4*)(smem + (pb - smem_u32(smem)) + (n * 32 + lane) * 16);
        if (r + 2 < 8) {
#pragma unroll
            for (int it = 0; it < 8; it++) {
                int idx = (it * 32 + lane) * 16;
                cp_async16(pb + idx, slot_base + (r + 2) * 4096 + idx);
            }
        }
        cp_commit();   // commit every iteration to keep group accounting uniform

        float a_[NSLOT] = {aa.x, aa.y, aa.z, aa.w, ab.x, ab.y, ab.z, ab.w};
        float na[NSLOT];
#pragma unroll
        for (int n = 0; n < NSLOT; n++) na[n] = a_[n] * 0.95f;

        float4 wm4 = make_float4(0.f, 0.f, 0.f, 0.f);
#pragma unroll
        for (int n = 0; n < NSLOT; n++) {
            wm4.x = fmaf(na[n], sl[n].x, wm4.x);
            wm4.y = fmaf(na[n], sl[n].y, wm4.y);
            wm4.z = fmaf(na[n], sl[n].z, wm4.z);
            wm4.w = fmaf(na[n], sl[n].w, wm4.w);
        }
        float gdp = fmaf(0.125f, dot4(wm4, wg1), dot4(sv, wg0));
        float sn2 = dot4(sv, sv);
        float du[NSLOT], ds[NSLOT], qn[NSLOT];
#pragma unroll
        for (int n = 0; n < NSLOT; n++) {
            du[n] = dot4(uv, sl[n]);
            ds[n] = dot4(sv, sl[n]);
            qn[n] = dot4(sl[n], sl[n]);
        }

#pragma unroll
        for (int o = 16; o; o >>= 1) {
#pragma unroll
            for (int n = 0; n < NSLOT; n++) {
                du[n] += __shfl_xor_sync(0xFFFFFFFFu, du[n], o);
                ds[n] += __shfl_xor_sync(0xFFFFFFFFu, ds[n], o);
                qn[n] += __shfl_xor_sync(0xFFFFFFFFu, qn[n], o);
            }
            sn2 += __shfl_xor_sync(0xFFFFFFFFu, sn2, o);
            gdp += __shfl_xor_sync(0xFFFFFFFFu, gdp, o);
        }

        const float gd = gdp + wgb;
        const float gate = 1.f / (1.f + __expf(-gd));
        const float stn = fmaxf(sqrtf(sn2), 1e-12f);
        const float inv_stn = 1.f / stn;

        const float inv_sqrt_d = 0.08838834764831845f;
        float attn[NSLOT];
        float mx = -INFINITY;
#pragma unroll
        for (int n = 0; n < NSLOT; n++) {
            attn[n] = du[n] * inv_sqrt_d * a_[n];
            mx = fmaxf(mx, attn[n]);
        }
        float se = 0.f;
#pragma unroll
        for (int n = 0; n < NSLOT; n++) {
            attn[n] = __expf(attn[n] - mx);
            se += attn[n];
        }
        const float inv_se = 1.f / se;

        float simmax = -INFINITY;
#pragma unroll
        for (int n = 0; n < NSLOT; n++) {
            float m = (na[n] > 0.01f) ? 1.f : 0.f;
            float c = ds[n] * inv_stn / fmaxf(sqrtf(qn[n]), 1e-12f);
            simmax = fmaxf(simmax, c * m);
        }
        const float novelty = 1.f - fminf(fmaxf(simmax, 0.f), 1.f);
        const bool do_write = (novelty > 0.3f) || (gate > 0.5f);

        int weakest = 0;
        float mn = na[0];
#pragma unroll
        for (int n = 1; n < NSLOT; n++)
            if (na[n] < mn) { mn = na[n]; weakest = n; }
        const int sel = do_write ? weakest : -1;

        float swv[NSLOT];
        float swmx = -INFINITY;
#pragma unroll
        for (int n = 0; n < NSLOT; n++) {
            swv[n] = (n == sel) ? 1.f : na[n];
            swmx = fmaxf(swmx, swv[n]);
        }
        float ssum = 0.f;
#pragma unroll
        for (int n = 0; n < NSLOT; n++) {
            swv[n] = __expf(swv[n] - swmx);
            ssum += swv[n];
        }
        const float inv_ss = 1.f / ssum;

        float4* orow4 = (float4*)(out + (size_t)b * OUTW);
        float4 ro = make_float4(0.f, 0.f, 0.f, 0.f);
        float4 sm = make_float4(0.f, 0.f, 0.f, 0.f);
#pragma unroll
        for (int n = 0; n < NSLOT; n++) {
            const float wa = attn[n] * inv_se;
            const float ws = swv[n] * inv_ss;
            float4 x = sl[n];
            float4 v = (n == sel) ? sv : x;
            ro.x = fmaf(wa, x.x, ro.x);  ro.y = fmaf(wa, x.y, ro.y);
            ro.z = fmaf(wa, x.z, ro.z);  ro.w = fmaf(wa, x.w, ro.w);
            sm.x = fmaf(ws, v.x, sm.x);  sm.y = fmaf(ws, v.y, sm.y);
            sm.z = fmaf(ws, v.z, sm.z);  sm.w = fmaf(ws, v.w, sm.w);
            __stcs(orow4 + 64 + n * 32 + lane, v);
        }
        __stcs(orow4 + lane, ro);
        *(float4*)(smU + lrow * 128 + lane * 4) = sm;   // S in-place
        if (lane < NSLOT) {
            float v = (lane == sel) ? 1.f : na[lane];
            out[(size_t)b * OUTW + 2 * D + NSLOT * D + lane] = v;
        }
    }
    asm volatile("cp.async.wait_group 0;" ::: "memory");
    __syncthreads();

    // ======== phase 3: stage S (smU) -> bf16 smem ========
#pragma unroll
    for (int i = 0; i < 8; i++) {
        int idx = tid + i * 256;
        int row = idx >> 5;
        int c4 = idx & 31;
        float4 v = *(const float4*)(smU + row * 128 + c4 * 4);
        unsigned h01 = pack_bf(v.x, v.y);
        unsigned h23 = pack_bf(v.z, v.w);
        unsigned l01 = pack_bf(v.x - lo_f(h01), v.y - hi_f(h01));
        unsigned l23 = pack_bf(v.z - lo_f(h23), v.w - hi_f(h23));
        int chunk = c4 >> 1, half = c4 & 1;
        int off = row * 256 + ((chunk ^ (row & 7)) << 4) + (half << 3);
        *(uint2*)(smA + off) = make_uint2(h01, h23);
        *(uint2*)(smA + 16384 + off) = make_uint2(l01, l23);
    }
    __syncthreads();

    // ======== GEMM2: summary = S @ Wf^T -> out[:,128:256] ========
    {
        float acc[8][4];
        mma_phase(smA, BF, wm, wn, lane, acc);
        const int row = brow + wm * 16 + (lane >> 2);
        const int cb = (lane & 3) << 1;
#pragma unroll
        for (int nt = 0; nt < 8; nt++) {
            const int col = D + wn * 64 + nt * 8 + cb;
            float* cp = out + (size_t)row * OUTW + col;
            *(float2*)cp = make_float2(acc[nt][0], acc[nt][1]);
            *(float2*)(cp + 8 * OUTW) = make_float2(acc[nt][2], acc[nt][3]);
        }
    }
}

// ---------------------------------------------------------------------------
extern "C" void kernel_launch(void* const* d_in, const int* in_sizes, int n_in,
                              void* d_out, int out_size) {
    const float* state = (const float*)d_in[0];
    const float* slots = (const float*)d_in[1];
    const float* acts  = (const float*)d_in[2];
    const float* Wq    = (const float*)d_in[3];
    const float* Wk    = (const float*)d_in[4];
    const float* Wg_w  = (const float*)d_in[5];
    const float* Wg_b  = (const float*)d_in[6];
    const float* Wf    = (const float*)d_in[7];
    float* out = (float*)d_out;

    const int B = in_sizes[0] / D;

    void *pBU, *pBF;
    cudaGetSymbolAddress(&pBU, g_BU);
    cudaGetSymbolAddress(&pBF, g_BF);

    static int attr_set = 0;
    if (!attr_set) {
        cudaFuncSetAttribute(fused_kernel,
                             cudaFuncAttributeMaxDynamicSharedMemorySize, 98304);
        attr_set = 1;
    }

    prep_kernel<<<256, 128>>>(Wq, Wk, Wf);
    fused_kernel<<<B / 64, 256, 98304>>>(state, slots, acts, Wg_w, Wg_b,
                                         (const uint4*)pBU, (const uint4*)pBF, out);
}